// round 15
// baseline (speedup 1.0000x reference)
#include <cuda_runtime.h>

// LatentDT: z[n,v] = clamp(min over edges on root->v path of +-(x[n].A[s]), 0, 1)
// At a live split (q>0): qL>0 iff p>0, qR>0 iff p<0 -> exactly ONE child
// survives per level -> stackless root-to-leaf descent, 11 writes per row.
//
// Proven-best structure (R9/R14): per-warp scalar fill (best DRAM pacing,
// 4.39 TB/s), DFS fully hidden under the fill. This round: 128-thread CTAs
// (2x CTA count -> finer wave balancing / less tail imbalance) + unroll 8.

#define DEPTH     10
#define NB_SPLIT  1023   // 2^10 - 1
#define NB_NODES  2047   // 2^11 - 1
#define KDIM      128

#define THREADS   128    // 4 warps/CTA, 1 row/warp

__global__ void __launch_bounds__(THREADS, 16) latentdt_kernel(
    const float* __restrict__ x,
    const float* __restrict__ A,
    float* __restrict__ out,
    int rows)
{
    const int row  = (blockIdx.x * blockDim.x + threadIdx.x) >> 5;
    const int lane = threadIdx.x & 31;
    if (row >= rows) return;

    // x row: 128 floats, 4 per lane (512B, coalesced).
    const float4 xv = __ldg(reinterpret_cast<const float4*>(
                                x + (size_t)row * KDIM) + lane);

    const float4* __restrict__ Af4 = reinterpret_cast<const float4*>(A);

    // Prefetch A[0] so the root dot's load latency hides under the fill.
    float4 av = __ldg(Af4 + lane);

    float* outrow = out + (size_t)row * NB_NODES;

    // Per-warp scalar zero fill of own row (measured-best DRAM pacing).
    #pragma unroll 8
    for (int idx = lane; idx < NB_NODES; idx += 32) outrow[idx] = 0.0f;
    __syncwarp();                      // order fill before scatter overwrites
    if (lane == 0) outrow[0] = 1.0f;   // root: clamp(1) = 1

    // ---- Stackless path descent: exactly one survivor per level ----
    int   node = 0;
    float q    = 1.0f;                 // path-min, always > 0 while looping

    #pragma unroll
    for (int d = 0; d < DEPTH; ++d) {
        // dot(x_row, A[node]): per-lane float4 FMA + butterfly reduce
        float p = fmaf(xv.x, av.x,
                  fmaf(xv.y, av.y,
                  fmaf(xv.z, av.z, xv.w * av.w)));
        p += __shfl_xor_sync(0xffffffffu, p, 16);
        p += __shfl_xor_sync(0xffffffffu, p, 8);
        p += __shfl_xor_sync(0xffffffffu, p, 4);
        p += __shfl_xor_sync(0xffffffffu, p, 2);
        p += __shfl_xor_sync(0xffffffffu, p, 1);
        // p warp-uniform.

        if (p > 0.0f) {                        // left child survives
            const int cl = 2 * node + 1;
            q = fminf(q, p);                   // <= 1 always
            if (lane == 0) outrow[cl] = q;
            node = cl;
        } else if (p < 0.0f) {                 // right child survives
            const int cr = 2 * node + 2;
            q = fminf(q, -p);
            if (lane == 0) outrow[cr] = q;
            node = cr;
        } else {
            break;                             // p == 0: both children clamp to 0
        }

        if (d < DEPTH - 1)                     // load next level's A row
            av = __ldg(Af4 + (size_t)node * (KDIM / 4) + lane);
    }
}

extern "C" void kernel_launch(void* const* d_in, const int* in_sizes, int n_in,
                              void* d_out, int out_size)
{
    const float* x = (const float*)d_in[0];   // [rows, 128]
    const float* A = (const float*)d_in[1];   // [1023, 128]
    float* out = (float*)d_out;               // [rows, 2047]

    const int rows = out_size / NB_NODES;     // 32768

    const int warps_per_block = THREADS / 32;
    const int blocks = (rows + warps_per_block - 1) / warps_per_block;
    latentdt_kernel<<<blocks, THREADS>>>(x, A, out, rows);
}

// round 16
// speedup vs baseline: 1.2879x; 1.2879x over previous
#include <cuda_runtime.h>

// LatentDT: z[n,v] = clamp(min over edges on root->v path of +-(x[n].A[s]), 0, 1)
// KEY: at a live split (q>0), qL>0 iff p>0 and qR>0 iff p<0 -> exactly ONE
// child survives each level. The "tree DFS" is a single root-to-leaf path:
// stackless, exactly DEPTH levels, 11 writes per row.
//
// FINAL (R9/R14 config, measured best across 12 experiments):
//  - 256-thread CTAs, 1 row/warp: 8 contiguous rows (64KB) per CTA gives the
//    best DRAM page locality (128-thread CTAs: -21% BW; cooperative fills,
//    .cs/.cg policies, SMEM+TMA staging, split kernels: all regressed).
//  - per-warp scalar fill paces DRAM writes best (4.39 TB/s measured).
//  - fused kernel time == isolated pure-memset time (~53 us) -> the path
//    descent is fully hidden; kernel is at the part's write roofline.

#define DEPTH     10
#define NB_SPLIT  1023   // 2^10 - 1
#define NB_NODES  2047   // 2^11 - 1
#define KDIM      128

__global__ void __launch_bounds__(256, 8) latentdt_kernel(
    const float* __restrict__ x,
    const float* __restrict__ A,
    float* __restrict__ out,
    int rows)
{
    const int row  = (blockIdx.x * blockDim.x + threadIdx.x) >> 5;
    const int lane = threadIdx.x & 31;
    if (row >= rows) return;

    // x row: 128 floats, 4 per lane (512B, coalesced).
    const float4 xv = __ldg(reinterpret_cast<const float4*>(
                                x + (size_t)row * KDIM) + lane);

    const float4* __restrict__ Af4 = reinterpret_cast<const float4*>(A);

    // Prefetch A[0] so the root dot's load latency hides under the fill.
    float4 av = __ldg(Af4 + lane);

    float* outrow = out + (size_t)row * NB_NODES;

    // Per-warp scalar zero fill of own row (measured-best DRAM pacing).
    for (int idx = lane; idx < NB_NODES; idx += 32) outrow[idx] = 0.0f;
    __syncwarp();                      // order fill before scatter overwrites
    if (lane == 0) outrow[0] = 1.0f;   // root: clamp(1) = 1

    // ---- Stackless path descent: exactly one survivor per level ----
    int   node = 0;
    float q    = 1.0f;                 // path-min, always > 0 while looping

    #pragma unroll
    for (int d = 0; d < DEPTH; ++d) {
        // dot(x_row, A[node]): per-lane float4 FMA + butterfly reduce
        float p = fmaf(xv.x, av.x,
                  fmaf(xv.y, av.y,
                  fmaf(xv.z, av.z, xv.w * av.w)));
        p += __shfl_xor_sync(0xffffffffu, p, 16);
        p += __shfl_xor_sync(0xffffffffu, p, 8);
        p += __shfl_xor_sync(0xffffffffu, p, 4);
        p += __shfl_xor_sync(0xffffffffu, p, 2);
        p += __shfl_xor_sync(0xffffffffu, p, 1);
        // p warp-uniform.

        if (p > 0.0f) {                        // left child survives
            const int cl = 2 * node + 1;
            q = fminf(q, p);                   // <= 1 always
            if (lane == 0) outrow[cl] = q;
            node = cl;
        } else if (p < 0.0f) {                 // right child survives
            const int cr = 2 * node + 2;
            q = fminf(q, -p);
            if (lane == 0) outrow[cr] = q;
            node = cr;
        } else {
            break;                             // p == 0: both children clamp to 0
        }

        if (d < DEPTH - 1)                     // load next level's A row
            av = __ldg(Af4 + (size_t)node * (KDIM / 4) + lane);
    }
}

extern "C" void kernel_launch(void* const* d_in, const int* in_sizes, int n_in,
                              void* d_out, int out_size)
{
    const float* x = (const float*)d_in[0];   // [rows, 128]
    const float* A = (const float*)d_in[1];   // [1023, 128]
    float* out = (float*)d_out;               // [rows, 2047]

    const int rows = out_size / NB_NODES;     // 32768

    const int threads = 256;                  // 8 warps/block, 1 row/warp
    const int blocks = (rows + 7) / 8;
    latentdt_kernel<<<blocks, threads>>>(x, A, out, rows);
}